// round 15
// baseline (speedup 1.0000x reference)
#include <cuda_runtime.h>
#include <cuda_bf16.h>
#include <cuda_fp16.h>
#include <math.h>
#include <stdint.h>

#define BATCH     1024
#define NF        256
#define NS        100000
#define INV_TEMP  20.0f
#define LOG2E     1.4426950408889634f
#define LN2F      0.6931471805599453f
#define SCALE2    (INV_TEMP * LOG2E)           /* folded into A at pack time */
#define SHIFT     128.0f                       /* fixed softmax shift (log2 domain) */
#define NTILE     352
#define WN        88
#define NFW       11
#define NBLK      ((NS + NTILE - 1) / NTILE)   /* 285 -> 1.93 waves */
#define MCHUNK    64
#define NCHUNKS   (BATCH / MCHUNK)             /* 16 */
#define LDSS      264                          /* 256 + 8 fp16 pad */

#define SMEM_BYTES (NTILE * LDSS * 2 + 64)     /* B slab only, ~186 KB */

/* A packed fragment-major fp16: [64 frag16 groups][16 ksteps][32 lanes] x 16B */
__device__ uint4 g_a_pk[64 * 16 * 32];
__device__ float g_pq[(size_t)NBLK * BATCH * 16];  /* per-quad partial sums */
__device__ float g_tlogit[BATCH];
__device__ float g_rownll[BATCH];
__device__ int   g_tstride;

// ---------------------------------------------------------------- helpers
__device__ __forceinline__ uint32_t sptr(const void* p) {
    return (uint32_t)__cvta_generic_to_shared(p);
}
__device__ __forceinline__ void ldsm4(uint32_t addr, uint32_t& r0, uint32_t& r1,
                                      uint32_t& r2, uint32_t& r3) {
    asm volatile("ldmatrix.sync.aligned.m8n8.x4.shared.b16 {%0,%1,%2,%3}, [%4];"
                 : "=r"(r0), "=r"(r1), "=r"(r2), "=r"(r3) : "r"(addr));
}
__device__ __forceinline__ void ldsm2(uint32_t addr, uint32_t& r0, uint32_t& r1) {
    asm volatile("ldmatrix.sync.aligned.m8n8.x2.shared.b16 {%0,%1}, [%2];"
                 : "=r"(r0), "=r"(r1) : "r"(addr));
}
// f16 x f16 -> f16 accumulate (potential 2x rate vs f32 acc)
__device__ __forceinline__ void mma16816h(uint32_t c[2], const uint32_t a[4],
                                          uint32_t b0, uint32_t b1) {
    asm volatile(
        "mma.sync.aligned.m16n8k16.row.col.f16.f16.f16.f16 "
        "{%0,%1},{%2,%3,%4,%5},{%6,%7},{%0,%1};"
        : "+r"(c[0]), "+r"(c[1])
        : "r"(a[0]), "r"(a[1]), "r"(a[2]), "r"(a[3]), "r"(b0), "r"(b1));
}

// ---------------------------------------------------------------- prep: pack A (fp16, pre-scaled) frag-major
__global__ void prep_kernel(const float* __restrict__ a) {
    int w = blockIdx.x * blockDim.x + threadIdx.x;   // word idx [0, 131072)
    if (w >= 64 * 16 * 32 * 4) return;
    int word = w & 3;
    int lane = (w >> 2) & 31;
    int ks   = (w >> 7) & 15;
    int g    = w >> 11;
    int qr = lane >> 2, qc = lane & 3;
    int row = g * 16 + qr + (word & 1) * 8;
    int col = ks * 16 + qc * 2 + (word >> 1) * 8;
    float f0 = a[row * NF + col]     * SCALE2;
    float f1 = a[row * NF + col + 1] * SCALE2;
    __half2 p = __floats2half2_rn(f0, f1);
    ((uint32_t*)g_a_pk)[w] = *(uint32_t*)&p;
}

__global__ void detect_kernel(const int* __restrict__ t32) {
    if (threadIdx.x == 0 && blockIdx.x == 0) {
        int s = 2;
        for (int i = 1; i < 512; i += 2)
            if (t32[i] != 0) { s = 1; break; }
        g_tstride = s;
    }
}

__global__ void tlogit_kernel(const float* __restrict__ a,
                              const int* __restrict__ t32,
                              const float* __restrict__ f) {
    int row = blockIdx.x;
    int tid = threadIdx.x;  // 256
    long long tgt = (long long)t32[row * g_tstride];
    float p = a[row * NF + tid] * f[tgt * NF + tid];
    for (int off = 16; off; off >>= 1) p += __shfl_xor_sync(~0u, p, off);
    __shared__ float sm[8];
    if ((tid & 31) == 0) sm[tid >> 5] = p;
    __syncthreads();
    if (tid == 0) {
        float s = 0.f;
        #pragma unroll
        for (int w = 0; w < 8; w++) s += sm[w];
        g_tlogit[row] = s * INV_TEMP;
    }
}

// ---------------------------------------------------------------- fused GEMM + fixed-shift softmax partials
extern __shared__ char smem_raw[];

__global__ void __launch_bounds__(256, 1) gemm_lse_kernel(const float* __restrict__ feats) {
    __half* Bs = (__half*)smem_raw;                  // [352][264] fp16

    const int tid  = threadIdx.x;                    // 256 threads, 8 warps
    const int lane = tid & 31, warp = tid >> 5;
    const int wm = warp & 1, wn = warp >> 1;         // 2x4 grid, 32x88 warp tiles
    const int nbase = blockIdx.x * NTILE;

    // Load feature slab once (fp32 -> fp16): 352 rows; OOB rows -> 0
    for (int i = tid; i < NTILE * (NF / 4); i += 256) {
        int r  = i >> 6;
        int c4 = i & 63;
        int srow = nbase + r;
        float4 v = make_float4(0.f, 0.f, 0.f, 0.f);
        if (srow < NS) v = ((const float4*)feats)[(size_t)srow * (NF / 4) + c4];
        __half2 p0 = __floats2half2_rn(v.x, v.y);
        __half2 p1 = __floats2half2_rn(v.z, v.w);
        uint2 u;
        u.x = *(uint32_t*)&p0;
        u.y = *(uint32_t*)&p1;
        *(uint2*)(Bs + r * LDSS + c4 * 4) = u;
    }

    const int bRow = (lane & 7) + ((lane >> 4) << 3), bKo = ((lane >> 3) & 1) << 3;
    const int bKo2 = ((lane >> 3) & 1) << 3;
    const int qr = lane >> 2, qc = lane & 3;

    uint32_t bAd[5], bAdT;
    #pragma unroll
    for (int t = 0; t < 5; t++)
        bAd[t] = sptr(Bs + (wn * WN + t * 16 + bRow) * LDSS + bKo);
    bAdT = sptr(Bs + (wn * WN + 80 + (lane & 7)) * LDSS + bKo2);

    __syncthreads();                      // the ONLY barrier: B slab ready

    const int mc0 = (2 * warp) & (NCHUNKS - 1);

    // split-K fp16 accumulators: ksteps 0-7 -> accL, 8-15 -> accH
    uint32_t accL[2][NFW][2], accH[2][NFW][2];
    uint32_t af[2][2][4];                 // double-buffered A frags (LDG.128)
    uint32_t bf[2][NFW][2];               // double-buffered B frags (ldsm)

    // preload kstep 0 of first chunk into buffer 0
    #pragma unroll
    for (int mf = 0; mf < 2; mf++) {
        uint4 v = __ldg(&g_a_pk[((mc0 * 4 + wm * 2 + mf) * 16 + 0) * 32 + lane]);
        af[0][mf][0] = v.x; af[0][mf][1] = v.y; af[0][mf][2] = v.z; af[0][mf][3] = v.w;
    }
    #pragma unroll
    for (int t = 0; t < 5; t++)
        ldsm4(bAd[t], bf[0][2*t][0], bf[0][2*t][1], bf[0][2*t+1][0], bf[0][2*t+1][1]);
    ldsm2(bAdT, bf[0][10][0], bf[0][10][1]);

    #pragma unroll 1
    for (int mcc = 0; mcc < NCHUNKS; mcc++) {
        const int mc = (mc0 + mcc) & (NCHUNKS - 1);

        #pragma unroll
        for (int mf = 0; mf < 2; mf++)
            #pragma unroll
            for (int nf = 0; nf < NFW; nf++)
                #pragma unroll
                for (int j = 0; j < 2; j++) {
                    accL[mf][nf][j] = 0u;
                    accH[mf][nf][j] = 0u;
                }

        #pragma unroll
        for (int ks = 0; ks < 16; ks++) {
            const int cur = ks & 1, nx = cur ^ 1;
            if (ks < 15 || mcc + 1 < NCHUNKS) {
                const int pmc = (ks < 15) ? mc : ((mc + 1) & (NCHUNKS - 1));
                const int pks = (ks < 15) ? (ks + 1) : 0;
                #pragma unroll
                for (int mf = 0; mf < 2; mf++) {
                    uint4 v = __ldg(&g_a_pk[((pmc * 4 + wm * 2 + mf) * 16 + pks) * 32 + lane]);
                    af[nx][mf][0] = v.x; af[nx][mf][1] = v.y;
                    af[nx][mf][2] = v.z; af[nx][mf][3] = v.w;
                }
                const uint32_t off = (uint32_t)pks * 32;
                #pragma unroll
                for (int t = 0; t < 5; t++)
                    ldsm4(bAd[t] + off, bf[nx][2*t][0], bf[nx][2*t][1],
                          bf[nx][2*t+1][0], bf[nx][2*t+1][1]);
                ldsm2(bAdT + off, bf[nx][10][0], bf[nx][10][1]);
            }
            if (ks < 8) {
                #pragma unroll
                for (int mf = 0; mf < 2; mf++)
                    #pragma unroll
                    for (int nf = 0; nf < NFW; nf++)
                        mma16816h(accL[mf][nf], af[cur][mf], bf[cur][nf][0], bf[cur][nf][1]);
            } else {
                #pragma unroll
                for (int mf = 0; mf < 2; mf++)
                    #pragma unroll
                    for (int nf = 0; nf < NFW; nf++)
                        mma16816h(accH[mf][nf], af[cur][mf], bf[cur][nf][0], bf[cur][nf][1]);
            }
        }

        // epilogue: combine half-K fp16 accs in fp32, fixed-shift exp2, STG
        {
            float s4[4] = {0.f, 0.f, 0.f, 0.f};
            #pragma unroll
            for (int mf = 0; mf < 2; mf++)
                #pragma unroll
                for (int hi = 0; hi < 2; hi++) {
                    float s = 0.f;
                    #pragma unroll
                    for (int nf = 0; nf < NFW; nf++) {
                        float2 lo = __half22float2(*(__half2*)&accL[mf][nf][hi]);
                        float2 hv = __half22float2(*(__half2*)&accH[mf][nf][hi]);
                        s += exp2f(lo.x + hv.x - SHIFT);
                        s += exp2f(lo.y + hv.y - SHIFT);
                    }
                    s4[mf * 2 + hi] = s;
                }
            #pragma unroll
            for (int t = 0; t < 4; t++) {
                const int mf = t >> 1, hi = t & 1;
                int rl = wm * 32 + mf * 16 + hi * 8 + qr;
                g_pq[((size_t)blockIdx.x * BATCH + mc * MCHUNK + rl) * 16 + wn * 4 + qc] = s4[t];
            }
        }
    }
}

// ---------------------------------------------------------------- cross-block merge: plain sum over 285x16 quads
__global__ void lse_kernel() {
    int row = blockIdx.x;
    int tid = threadIdx.x;  // 256
    float S = 0.f;
    const int total = NBLK * 16;
    for (int v = tid; v < total; v += 256) {
        int blk = v >> 4, idx = v & 15;
        S += g_pq[((size_t)blk * BATCH + row) * 16 + idx];
    }
    for (int off = 16; off; off >>= 1) S += __shfl_xor_sync(~0u, S, off);
    __shared__ float ss[8];
    if ((tid & 31) == 0) ss[tid >> 5] = S;
    __syncthreads();
    if (tid == 0) {
        float Sv = 0.f;
        #pragma unroll
        for (int i = 0; i < 8; i++) Sv += ss[i];
        g_rownll[row] = (SHIFT + log2f(Sv)) * LN2F - g_tlogit[row];
    }
}

__global__ void mean_kernel(float* __restrict__ out) {
    __shared__ float sm[32];
    int tid = threadIdx.x;  // 1024
    float v = g_rownll[tid];
    for (int off = 16; off; off >>= 1) v += __shfl_xor_sync(~0u, v, off);
    if ((tid & 31) == 0) sm[tid >> 5] = v;
    __syncthreads();
    if (tid < 32) {
        float x = sm[tid];
        for (int off = 16; off; off >>= 1) x += __shfl_xor_sync(~0u, x, off);
        if (tid == 0) out[0] = x / (float)BATCH;
    }
}

// ---------------------------------------------------------------- launch
extern "C" void kernel_launch(void* const* d_in, const int* in_sizes, int n_in,
                              void* d_out, int out_size) {
    const float* a   = (const float*)d_in[0];   // inputs   [1024,256] f32
    const int*   t32 = (const int*)d_in[1];     // targets  [1024] i64/i32
    const float* f   = (const float*)d_in[2];   // features [100000,256] f32
    float* out = (float*)d_out;

    cudaFuncSetAttribute(gemm_lse_kernel,
                         cudaFuncAttributeMaxDynamicSharedMemorySize, SMEM_BYTES);

    prep_kernel<<<512, 256>>>(a);
    detect_kernel<<<1, 32>>>(t32);
    tlogit_kernel<<<BATCH, 256>>>(a, t32, f);
    gemm_lse_kernel<<<NBLK, 256, SMEM_BYTES>>>(f);
    lse_kernel<<<BATCH, 256>>>();
    mean_kernel<<<1, 1024>>>(out);
}